// round 4
// baseline (speedup 1.0000x reference)
#include <cuda_runtime.h>

#define RES      64
#define R3       (RES * RES * RES)      // 262144
#define NWORDS   (R3 / 32)              // 8192  (32 KB bitmask)
#define NB       888                    // 148 SMs * 6 blocks
#define NHALF    (NB / 2)               // 444 per transform family
#define NT       256

// ---- scratch (no allocations allowed) --------------------------------------
__device__    float4   g_table[R3];     // closest point per voxel (w unused)
__device__    unsigned g_bits[NWORDS];  // voxel occupancy bitmask
__device__    float    g_params[48];    // [t*5+j]: refl ; [16+t*9+j]: rot matrix
__constant__  float    c_params[48];    // same, via D2D memcpy (graph-capturable)
__device__    float    g_partials[NB];
__device__    int      g_counter;

// ---- prep: params + float4 table + bitmask + counter reset (one kernel) -----
__global__ void prep_k(const float* __restrict__ cp,
                       const int*   __restrict__ vox,
                       const float* __restrict__ planes,
                       const float* __restrict__ axes) {
    int i = blockIdx.x * blockDim.x + threadIdx.x;
    if (i == 0) {
        g_counter = 0;
#pragma unroll
        for (int t = 0; t < 3; t++) {
            float nx = planes[4*t+0], ny = planes[4*t+1],
                  nz = planes[4*t+2], d  = planes[4*t+3];
            float s = 2.0f / (nx*nx + ny*ny + nz*nz);
            g_params[t*5+0] = nx;
            g_params[t*5+1] = ny;
            g_params[t*5+2] = nz;
            g_params[t*5+3] = s;
            g_params[t*5+4] = s * d;
        }
#pragma unroll
        for (int t = 0; t < 3; t++) {
            float w = axes[4*t+0], x = axes[4*t+1],
                  y = axes[4*t+2], z = axes[4*t+3];
            // q p q* (pure p, q unnormalized) = [(w^2-|v|^2)I + 2 v v^T + 2 w [v]x] p
            float* m = &g_params[16 + t*9];
            m[0] = w*w + x*x - y*y - z*z;
            m[1] = 2.0f * (x*y - w*z);
            m[2] = 2.0f * (x*z + w*y);
            m[3] = 2.0f * (x*y + w*z);
            m[4] = w*w - x*x + y*y - z*z;
            m[5] = 2.0f * (y*z - w*x);
            m[6] = 2.0f * (x*z - w*y);
            m[7] = 2.0f * (y*z + w*x);
            m[8] = w*w - x*x - y*y + z*z;
        }
    }
    if (i < R3) {
        float4 v;
        v.x = cp[3*i + 0];
        v.y = cp[3*i + 1];
        v.z = cp[3*i + 2];
        v.w = 0.0f;
        g_table[i] = v;
    }
    if (i < NWORDS) {
        unsigned w = 0u;
#pragma unroll 8
        for (int j = 0; j < 32; j++)
            if (vox[i*32 + j] != 0) w |= (1u << j);
        g_bits[i] = w;
    }
}

// ---- voxel index from transformed coords ------------------------------------
__device__ __forceinline__ int vidx(float x, float y, float z) {
    int ix = min(max(__float2int_rd(x * 64.0f), 0), 63);
    int iy = min(max(__float2int_rd(y * 64.0f), 0), 63);
    int iz = min(max(__float2int_rd(z * 64.0f), 0), 63);
    return (ix << 12) | (iy << 6) | iz;
}

// 3 taps for one point: indices -> mask -> batched gathers
__device__ __forceinline__ float taps3(const float tx[3], const float ty[3],
                                       const float tz[3],
                                       const unsigned* __restrict__ s_bits) {
    int  idx[3];
    bool live[3];
#pragma unroll
    for (int t = 0; t < 3; t++) {
        idx[t]  = vidx(tx[t], ty[t], tz[t]);
        live[t] = (s_bits[idx[t] >> 5] >> (idx[t] & 31)) & 1u;
    }
    float acc = 0.0f;
#pragma unroll
    for (int t = 0; t < 3; t++) {
        if (live[t]) {
            float4 c = __ldg(&g_table[idx[t]]);
            float dx = tx[t] - c.x, dy = ty[t] - c.y, dz = tz[t] - c.z;
            acc += sqrtf(fmaf(dx, dx, fmaf(dy, dy, dz * dz)));
        }
    }
    return acc;
}

// params read straight from __constant__ (LDC) — keeps them out of the RF
__device__ __forceinline__ float point_refl(float x, float y, float z,
                                            const unsigned* __restrict__ s_bits) {
    float tx[3], ty[3], tz[3];
#pragma unroll
    for (int t = 0; t < 3; t++) {
        float nx = c_params[t*5+0], ny = c_params[t*5+1], nz = c_params[t*5+2];
        float dot  = fmaf(x, nx, fmaf(y, ny, z * nz));
        float coef = fmaf(dot, c_params[t*5+3], c_params[t*5+4]);
        tx[t] = fmaf(-coef, nx, x);
        ty[t] = fmaf(-coef, ny, y);
        tz[t] = fmaf(-coef, nz, z);
    }
    return taps3(tx, ty, tz, s_bits);
}

__device__ __forceinline__ float point_rot(float x, float y, float z,
                                           const unsigned* __restrict__ s_bits) {
    float tx[3], ty[3], tz[3];
#pragma unroll
    for (int t = 0; t < 3; t++) {
        const float* m = &c_params[16 + t*9];
        tx[t] = fmaf(x, m[0], fmaf(y, m[1], z * m[2]));
        ty[t] = fmaf(x, m[3], fmaf(y, m[4], z * m[5]));
        tz[t] = fmaf(x, m[6], fmaf(y, m[7], z * m[8]));
    }
    return taps3(tx, ty, tz, s_bits);
}

// ---- main kernel: blocks [0,NHALF) do reflections, [NHALF,NB) rotations ------
__global__ void __launch_bounds__(NT, 6)
symmetry_main_k(const float* __restrict__ sp, int npts, float* __restrict__ out) {
    __shared__ unsigned s_bits[NWORDS];   // 32 KB
    __shared__ float    s_red[NT / 32];
    __shared__ bool     s_last;

    for (int i = threadIdx.x; i < NWORDS; i += NT)
        s_bits[i] = g_bits[i];
    __syncthreads();

    const bool is_rot = (blockIdx.x >= NHALF);
    const int  bid    = is_rot ? (blockIdx.x - NHALF) : blockIdx.x;

    const float4* sp4 = (const float4*)sp;
    const int ngroups = npts >> 2;     // 4 points = 3 float4
    const int stride  = NHALF * NT;
    const int tail    = npts & 3;
    float acc = 0.0f;

    if (!is_rot) {
        for (int g = bid * NT + threadIdx.x; g < ngroups; g += stride) {
            float4 A = __ldg(&sp4[3*g + 0]);
            float4 B = __ldg(&sp4[3*g + 1]);
            float4 C = __ldg(&sp4[3*g + 2]);
            acc += point_refl(A.x, A.y, A.z, s_bits);
            acc += point_refl(A.w, B.x, B.y, s_bits);
            acc += point_refl(B.z, B.w, C.x, s_bits);
            acc += point_refl(C.y, C.z, C.w, s_bits);
        }
        if (tail && bid == 0 && threadIdx.x < tail) {
            int i = npts - tail + threadIdx.x;
            acc += point_refl(sp[3*i], sp[3*i+1], sp[3*i+2], s_bits);
        }
    } else {
        for (int g = bid * NT + threadIdx.x; g < ngroups; g += stride) {
            float4 A = __ldg(&sp4[3*g + 0]);
            float4 B = __ldg(&sp4[3*g + 1]);
            float4 C = __ldg(&sp4[3*g + 2]);
            acc += point_rot(A.x, A.y, A.z, s_bits);
            acc += point_rot(A.w, B.x, B.y, s_bits);
            acc += point_rot(B.z, B.w, C.x, s_bits);
            acc += point_rot(C.y, C.z, C.w, s_bits);
        }
        if (tail && bid == 0 && threadIdx.x < tail) {
            int i = npts - tail + threadIdx.x;
            acc += point_rot(sp[3*i], sp[3*i+1], sp[3*i+2], s_bits);
        }
    }

    // deterministic block reduction
#pragma unroll
    for (int o = 16; o; o >>= 1)
        acc += __shfl_xor_sync(0xFFFFFFFFu, acc, o);
    int lane = threadIdx.x & 31;
    int wid  = threadIdx.x >> 5;
    if (lane == 0) s_red[wid] = acc;
    __syncthreads();
    if (threadIdx.x == 0) {
        float v = 0.0f;
#pragma unroll
        for (int w = 0; w < NT / 32; w++) v += s_red[w];
        g_partials[blockIdx.x] = v;
        __threadfence();
        unsigned old = atomicAdd(&g_counter, 1);
        s_last = (old == (unsigned)(gridDim.x - 1));
    }
    __syncthreads();

    // last-arriving block performs the final deterministic reduction
    if (s_last) {
        __threadfence();
        float v = 0.0f;
        for (int i = threadIdx.x; i < NB; i += NT)
            v += g_partials[i];
#pragma unroll
        for (int o = 16; o; o >>= 1)
            v += __shfl_xor_sync(0xFFFFFFFFu, v, o);
        if (lane == 0) s_red[wid] = v;
        __syncthreads();
        if (threadIdx.x == 0) {
            float u = 0.0f;
#pragma unroll
            for (int w = 0; w < NT / 32; w++) u += s_red[w];
            out[0] = u / (float)npts;
        }
    }
}

// ---- launch ------------------------------------------------------------------
extern "C" void kernel_launch(void* const* d_in, const int* in_sizes, int n_in,
                              void* d_out, int out_size) {
    const float* sp     = (const float*)d_in[0];   // sample_points (N,3)
    const float* cp     = (const float*)d_in[1];   // closest_points (R^3,3)
    const int*   vox    = (const int*)  d_in[2];   // voxels (R^3,)
    const float* planes = (const float*)d_in[3];   // (3,4)
    const float* axes   = (const float*)d_in[4];   // (3,4)
    int npts = in_sizes[0] / 3;

    prep_k<<<(R3 + 255) / 256, 256>>>(cp, vox, planes, axes);

    // copy device-computed params into __constant__ (D2D memcpy node, capturable)
    void* src = nullptr;
    cudaGetSymbolAddress(&src, g_params);
    cudaMemcpyToSymbolAsync(c_params, src, 48 * sizeof(float), 0,
                            cudaMemcpyDeviceToDevice, 0);

    symmetry_main_k<<<NB, NT>>>(sp, npts, (float*)d_out);
}

// round 5
// speedup vs baseline: 1.2224x; 1.2224x over previous
#include <cuda_runtime.h>

#define RES      64
#define R3       (RES * RES * RES)      // 262144
#define NWORDS   (R3 / 32)              // 8192  (32 KB bitmask)
#define NGROUP   148                    // blocks per transform (1/SM wave slice)
#define NB       (6 * NGROUP)           // 888 total = 6 blocks/SM
#define NT       256

// ---- scratch (no allocations allowed) --------------------------------------
__device__ float4   g_table[R3];        // closest point per voxel (w unused)
__device__ unsigned g_bits[NWORDS];     // voxel occupancy bitmask
__device__ float    g_params[48];       // [t*5+j]: refl ; [16+t*9+j]: rot matrix
__device__ float    g_partials[NB];
__device__ int      g_counter;

// ---- prep: params + float4 table + bitmask + counter reset (one kernel) -----
__global__ void prep_k(const float* __restrict__ cp,
                       const int*   __restrict__ vox,
                       const float* __restrict__ planes,
                       const float* __restrict__ axes) {
    int i = blockIdx.x * blockDim.x + threadIdx.x;
    if (i == 0) {
        g_counter = 0;
#pragma unroll
        for (int t = 0; t < 3; t++) {
            float nx = planes[4*t+0], ny = planes[4*t+1],
                  nz = planes[4*t+2], d  = planes[4*t+3];
            float s = 2.0f / (nx*nx + ny*ny + nz*nz);
            g_params[t*5+0] = nx;
            g_params[t*5+1] = ny;
            g_params[t*5+2] = nz;
            g_params[t*5+3] = s;
            g_params[t*5+4] = s * d;
        }
#pragma unroll
        for (int t = 0; t < 3; t++) {
            float w = axes[4*t+0], x = axes[4*t+1],
                  y = axes[4*t+2], z = axes[4*t+3];
            // q p q* (pure p, q unnormalized) = [(w^2-|v|^2)I + 2 v v^T + 2 w [v]x] p
            float* m = &g_params[16 + t*9];
            m[0] = w*w + x*x - y*y - z*z;
            m[1] = 2.0f * (x*y - w*z);
            m[2] = 2.0f * (x*z + w*y);
            m[3] = 2.0f * (x*y + w*z);
            m[4] = w*w - x*x + y*y - z*z;
            m[5] = 2.0f * (y*z - w*x);
            m[6] = 2.0f * (x*z - w*y);
            m[7] = 2.0f * (y*z + w*x);
            m[8] = w*w - x*x - y*y + z*z;
        }
    }
    if (i < R3) {
        float4 v;
        v.x = cp[3*i + 0];
        v.y = cp[3*i + 1];
        v.z = cp[3*i + 2];
        v.w = 0.0f;
        g_table[i] = v;
    }
    if (i < NWORDS) {
        unsigned w = 0u;
#pragma unroll 8
        for (int j = 0; j < 32; j++)
            if (vox[i*32 + j] != 0) w |= (1u << j);
        g_bits[i] = w;
    }
}

// ---- voxel index from transformed coords ------------------------------------
__device__ __forceinline__ int vidx(float x, float y, float z) {
    int ix = min(max(__float2int_rd(x * 64.0f), 0), 63);
    int iy = min(max(__float2int_rd(y * 64.0f), 0), 63);
    int iz = min(max(__float2int_rd(z * 64.0f), 0), 63);
    return (ix << 12) | (iy << 6) | iz;
}

// 4 taps (4 points, one transform): indices -> mask -> batched gathers
__device__ __forceinline__ float taps4(const float tx[4], const float ty[4],
                                       const float tz[4],
                                       const unsigned* __restrict__ s_bits) {
    int  idx[4];
    bool live[4];
#pragma unroll
    for (int k = 0; k < 4; k++) {
        idx[k]  = vidx(tx[k], ty[k], tz[k]);
        live[k] = (s_bits[idx[k] >> 5] >> (idx[k] & 31)) & 1u;
    }
    float acc = 0.0f;
#pragma unroll
    for (int k = 0; k < 4; k++) {
        if (live[k]) {
            float4 c = __ldg(&g_table[idx[k]]);
            float dx = tx[k] - c.x, dy = ty[k] - c.y, dz = tz[k] - c.z;
            acc += sqrtf(fmaf(dx, dx, fmaf(dy, dy, dz * dz)));
        }
    }
    return acc;
}

// ---- main kernel: 6 grid segments, one transform each -----------------------
__global__ void __launch_bounds__(NT, 6)
symmetry_main_k(const float* __restrict__ sp, int npts, float* __restrict__ out) {
    __shared__ unsigned s_bits[NWORDS];   // 32 KB
    __shared__ float    s_red[NT / 32];
    __shared__ bool     s_last;

    for (int i = threadIdx.x; i < NWORDS; i += NT)
        s_bits[i] = g_bits[i];
    __syncthreads();

    const int fam = blockIdx.x / NGROUP;   // 0..5 (uniform per block)
    const int bid = blockIdx.x % NGROUP;

    const float4* sp4 = (const float4*)sp;
    const int ngroups = npts >> 2;     // 4 points = 3 float4
    const int stride  = NGROUP * NT;
    const int tail    = npts & 3;
    float acc = 0.0f;

    if (fam < 3) {
        // reflection: 5 register-resident params
        const float nx = g_params[fam*5+0], ny = g_params[fam*5+1],
                    nz = g_params[fam*5+2], s  = g_params[fam*5+3],
                    sd = g_params[fam*5+4];

        for (int g = bid * NT + threadIdx.x; g < ngroups; g += stride) {
            float4 A = __ldg(&sp4[3*g + 0]);
            float4 B = __ldg(&sp4[3*g + 1]);
            float4 C = __ldg(&sp4[3*g + 2]);
            float X[4] = {A.x, A.w, B.z, C.y};
            float Y[4] = {A.y, B.x, B.w, C.z};
            float Z[4] = {A.z, B.y, C.x, C.w};
            float tx[4], ty[4], tz[4];
#pragma unroll
            for (int k = 0; k < 4; k++) {
                float dot  = fmaf(X[k], nx, fmaf(Y[k], ny, Z[k] * nz));
                float coef = fmaf(dot, s, sd);
                tx[k] = fmaf(-coef, nx, X[k]);
                ty[k] = fmaf(-coef, ny, Y[k]);
                tz[k] = fmaf(-coef, nz, Z[k]);
            }
            acc += taps4(tx, ty, tz, s_bits);
        }
        if (tail && bid == 0 && threadIdx.x < tail) {
            int i = npts - tail + threadIdx.x;
            float x = sp[3*i], y = sp[3*i+1], z = sp[3*i+2];
            float dot  = fmaf(x, nx, fmaf(y, ny, z * nz));
            float coef = fmaf(dot, s, sd);
            float tx = fmaf(-coef, nx, x), ty = fmaf(-coef, ny, y),
                  tz = fmaf(-coef, nz, z);
            int idx = vidx(tx, ty, tz);
            if ((s_bits[idx >> 5] >> (idx & 31)) & 1u) {
                float4 c = __ldg(&g_table[idx]);
                float dx = tx - c.x, dy = ty - c.y, dz = tz - c.z;
                acc += sqrtf(fmaf(dx, dx, fmaf(dy, dy, dz * dz)));
            }
        }
    } else {
        // rotation: 9 register-resident params
        const int t = fam - 3;
        float m0 = g_params[16+t*9+0], m1 = g_params[16+t*9+1],
              m2 = g_params[16+t*9+2], m3 = g_params[16+t*9+3],
              m4 = g_params[16+t*9+4], m5 = g_params[16+t*9+5],
              m6 = g_params[16+t*9+6], m7 = g_params[16+t*9+7],
              m8 = g_params[16+t*9+8];

        for (int g = bid * NT + threadIdx.x; g < ngroups; g += stride) {
            float4 A = __ldg(&sp4[3*g + 0]);
            float4 B = __ldg(&sp4[3*g + 1]);
            float4 C = __ldg(&sp4[3*g + 2]);
            float X[4] = {A.x, A.w, B.z, C.y};
            float Y[4] = {A.y, B.x, B.w, C.z};
            float Z[4] = {A.z, B.y, C.x, C.w};
            float tx[4], ty[4], tz[4];
#pragma unroll
            for (int k = 0; k < 4; k++) {
                tx[k] = fmaf(X[k], m0, fmaf(Y[k], m1, Z[k] * m2));
                ty[k] = fmaf(X[k], m3, fmaf(Y[k], m4, Z[k] * m5));
                tz[k] = fmaf(X[k], m6, fmaf(Y[k], m7, Z[k] * m8));
            }
            acc += taps4(tx, ty, tz, s_bits);
        }
        if (tail && bid == 0 && threadIdx.x < tail) {
            int i = npts - tail + threadIdx.x;
            float x = sp[3*i], y = sp[3*i+1], z = sp[3*i+2];
            float tx = fmaf(x, m0, fmaf(y, m1, z * m2));
            float ty = fmaf(x, m3, fmaf(y, m4, z * m5));
            float tz = fmaf(x, m6, fmaf(y, m7, z * m8));
            int idx = vidx(tx, ty, tz);
            if ((s_bits[idx >> 5] >> (idx & 31)) & 1u) {
                float4 c = __ldg(&g_table[idx]);
                float dx = tx - c.x, dy = ty - c.y, dz = tz - c.z;
                acc += sqrtf(fmaf(dx, dx, fmaf(dy, dy, dz * dz)));
            }
        }
    }

    // deterministic block reduction
#pragma unroll
    for (int o = 16; o; o >>= 1)
        acc += __shfl_xor_sync(0xFFFFFFFFu, acc, o);
    int lane = threadIdx.x & 31;
    int wid  = threadIdx.x >> 5;
    if (lane == 0) s_red[wid] = acc;
    __syncthreads();
    if (threadIdx.x == 0) {
        float v = 0.0f;
#pragma unroll
        for (int w = 0; w < NT / 32; w++) v += s_red[w];
        g_partials[blockIdx.x] = v;
        __threadfence();
        unsigned old = atomicAdd(&g_counter, 1);
        s_last = (old == (unsigned)(gridDim.x - 1));
    }
    __syncthreads();

    // last-arriving block performs the final deterministic reduction
    if (s_last) {
        __threadfence();
        float v = 0.0f;
        for (int i = threadIdx.x; i < NB; i += NT)
            v += g_partials[i];
#pragma unroll
        for (int o = 16; o; o >>= 1)
            v += __shfl_xor_sync(0xFFFFFFFFu, v, o);
        if (lane == 0) s_red[wid] = v;
        __syncthreads();
        if (threadIdx.x == 0) {
            float u = 0.0f;
#pragma unroll
            for (int w = 0; w < NT / 32; w++) u += s_red[w];
            out[0] = u / (float)npts;
        }
    }
}

// ---- launch ------------------------------------------------------------------
extern "C" void kernel_launch(void* const* d_in, const int* in_sizes, int n_in,
                              void* d_out, int out_size) {
    const float* sp     = (const float*)d_in[0];   // sample_points (N,3)
    const float* cp     = (const float*)d_in[1];   // closest_points (R^3,3)
    const int*   vox    = (const int*)  d_in[2];   // voxels (R^3,)
    const float* planes = (const float*)d_in[3];   // (3,4)
    const float* axes   = (const float*)d_in[4];   // (3,4)
    int npts = in_sizes[0] / 3;

    prep_k<<<(R3 + 255) / 256, 256>>>(cp, vox, planes, axes);
    symmetry_main_k<<<NB, NT>>>(sp, npts, (float*)d_out);
}

// round 6
// speedup vs baseline: 1.7341x; 1.4186x over previous
#include <cuda_runtime.h>

#define RES      64
#define R3       (RES * RES * RES)      // 262144
#define NWORDS   (R3 / 32)              // 8192  (32 KB bitmask)
#define NB       592                    // 148 SMs * 4 blocks
#define NHALF    (NB / 2)               // 296 per transform family
#define NT       256

// ---- scratch (no allocations allowed) --------------------------------------
__device__ float4   g_table[R3];        // closest point per voxel (w unused)
__device__ unsigned g_bits[NWORDS];     // voxel occupancy bitmask
__device__ float    g_params[48];       // [t*5+j]: refl ; [16+t*9+j]: rot matrix
__device__ float    g_partials[NB];
__device__ int      g_counter;

// ---- prep: params + float4 table + bitmask + counter reset (one kernel) -----
__global__ void prep_k(const float* __restrict__ cp,
                       const int*   __restrict__ vox,
                       const float* __restrict__ planes,
                       const float* __restrict__ axes) {
    int i = blockIdx.x * blockDim.x + threadIdx.x;
    if (i == 0) {
        g_counter = 0;
#pragma unroll
        for (int t = 0; t < 3; t++) {
            float nx = planes[4*t+0], ny = planes[4*t+1],
                  nz = planes[4*t+2], d  = planes[4*t+3];
            float s = 2.0f / (nx*nx + ny*ny + nz*nz);
            g_params[t*5+0] = nx;
            g_params[t*5+1] = ny;
            g_params[t*5+2] = nz;
            g_params[t*5+3] = s;
            g_params[t*5+4] = s * d;
        }
#pragma unroll
        for (int t = 0; t < 3; t++) {
            float w = axes[4*t+0], x = axes[4*t+1],
                  y = axes[4*t+2], z = axes[4*t+3];
            // q p q* (pure p, q unnormalized) = [(w^2-|v|^2)I + 2 v v^T + 2 w [v]x] p
            float* m = &g_params[16 + t*9];
            m[0] = w*w + x*x - y*y - z*z;
            m[1] = 2.0f * (x*y - w*z);
            m[2] = 2.0f * (x*z + w*y);
            m[3] = 2.0f * (x*y + w*z);
            m[4] = w*w - x*x + y*y - z*z;
            m[5] = 2.0f * (y*z - w*x);
            m[6] = 2.0f * (x*z - w*y);
            m[7] = 2.0f * (y*z + w*x);
            m[8] = w*w - x*x - y*y + z*z;
        }
    }
    if (i < R3) {
        float4 v;
        v.x = cp[3*i + 0];
        v.y = cp[3*i + 1];
        v.z = cp[3*i + 2];
        v.w = 0.0f;
        g_table[i] = v;
    }
    if (i < NWORDS) {
        unsigned w = 0u;
#pragma unroll 8
        for (int j = 0; j < 32; j++)
            if (vox[i*32 + j] != 0) w |= (1u << j);
        g_bits[i] = w;
    }
}

// ---- voxel index from transformed coords ------------------------------------
__device__ __forceinline__ int vidx(float x, float y, float z) {
    int ix = min(max(__float2int_rd(x * 64.0f), 0), 63);
    int iy = min(max(__float2int_rd(y * 64.0f), 0), 63);
    int iz = min(max(__float2int_rd(z * 64.0f), 0), 63);
    return (ix << 12) | (iy << 6) | iz;
}

// 3 branchless taps for one point: dead lanes gather entry 0 (broadcast line),
// contribution zeroed by mask multiply. No BSSY/BSYNC, loads fully batchable.
__device__ __forceinline__ float taps3(const float tx[3], const float ty[3],
                                       const float tz[3],
                                       const unsigned* __restrict__ s_bits) {
    int   eidx[3];
    float mskf[3];
#pragma unroll
    for (int t = 0; t < 3; t++) {
        int idx  = vidx(tx[t], ty[t], tz[t]);
        bool live = (s_bits[idx >> 5] >> (idx & 31)) & 1u;
        eidx[t] = live ? idx : 0;
        mskf[t] = live ? 1.0f : 0.0f;
    }
    float acc = 0.0f;
#pragma unroll
    for (int t = 0; t < 3; t++) {
        float4 c = __ldg(&g_table[eidx[t]]);
        float dx = tx[t] - c.x, dy = ty[t] - c.y, dz = tz[t] - c.z;
        float d2 = fmaxf(fmaf(dx, dx, fmaf(dy, dy, dz * dz)), 1e-30f);
        float dist = d2 * rsqrtf(d2);          // sqrt(d2), 1 MUFU + 1 FMUL
        acc = fmaf(mskf[t], dist, acc);
    }
    return acc;
}

__device__ __forceinline__ float point_refl(float x, float y, float z,
                                            const float pn[3][5],
                                            const unsigned* __restrict__ s_bits) {
    float tx[3], ty[3], tz[3];
#pragma unroll
    for (int t = 0; t < 3; t++) {
        float dot  = fmaf(x, pn[t][0], fmaf(y, pn[t][1], z * pn[t][2]));
        float coef = fmaf(dot, pn[t][3], pn[t][4]);
        tx[t] = fmaf(-coef, pn[t][0], x);
        ty[t] = fmaf(-coef, pn[t][1], y);
        tz[t] = fmaf(-coef, pn[t][2], z);
    }
    return taps3(tx, ty, tz, s_bits);
}

__device__ __forceinline__ float point_rot(float x, float y, float z,
                                           const float m[3][9],
                                           const unsigned* __restrict__ s_bits) {
    float tx[3], ty[3], tz[3];
#pragma unroll
    for (int t = 0; t < 3; t++) {
        tx[t] = fmaf(x, m[t][0], fmaf(y, m[t][1], z * m[t][2]));
        ty[t] = fmaf(x, m[t][3], fmaf(y, m[t][4], z * m[t][5]));
        tz[t] = fmaf(x, m[t][6], fmaf(y, m[t][7], z * m[t][8]));
    }
    return taps3(tx, ty, tz, s_bits);
}

// ---- main kernel: blocks [0,NHALF) do reflections, [NHALF,NB) rotations ------
__global__ void __launch_bounds__(NT, 4)
symmetry_main_k(const float* __restrict__ sp, int npts, float* __restrict__ out) {
    __shared__ unsigned s_bits[NWORDS];   // 32 KB
    __shared__ float    s_red[NT / 32];
    __shared__ bool     s_last;

    for (int i = threadIdx.x; i < NWORDS; i += NT)
        s_bits[i] = g_bits[i];
    __syncthreads();

    const bool is_rot = (blockIdx.x >= NHALF);
    const int  bid    = is_rot ? (blockIdx.x - NHALF) : blockIdx.x;

    const float4* sp4 = (const float4*)sp;
    const int ngroups = npts >> 2;     // 4 points = 3 float4
    const int stride  = NHALF * NT;
    const int tail    = npts & 3;
    float acc = 0.0f;

    if (!is_rot) {
        float pn[3][5];
#pragma unroll
        for (int t = 0; t < 3; t++)
#pragma unroll
            for (int j = 0; j < 5; j++) pn[t][j] = g_params[t*5 + j];

        for (int g = bid * NT + threadIdx.x; g < ngroups; g += stride) {
            float4 A = __ldg(&sp4[3*g + 0]);
            float4 B = __ldg(&sp4[3*g + 1]);
            float4 C = __ldg(&sp4[3*g + 2]);
            float X[4] = {A.x, A.w, B.z, C.y};
            float Y[4] = {A.y, B.x, B.w, C.z};
            float Z[4] = {A.z, B.y, C.x, C.w};
#pragma unroll
            for (int k = 0; k < 4; k++)
                acc += point_refl(X[k], Y[k], Z[k], pn, s_bits);
        }
        if (tail && bid == 0 && threadIdx.x < tail) {
            int i = npts - tail + threadIdx.x;
            acc += point_refl(sp[3*i], sp[3*i+1], sp[3*i+2], pn, s_bits);
        }
    } else {
        float m[3][9];
#pragma unroll
        for (int t = 0; t < 3; t++)
#pragma unroll
            for (int j = 0; j < 9; j++) m[t][j] = g_params[16 + t*9 + j];

        for (int g = bid * NT + threadIdx.x; g < ngroups; g += stride) {
            float4 A = __ldg(&sp4[3*g + 0]);
            float4 B = __ldg(&sp4[3*g + 1]);
            float4 C = __ldg(&sp4[3*g + 2]);
            float X[4] = {A.x, A.w, B.z, C.y};
            float Y[4] = {A.y, B.x, B.w, C.z};
            float Z[4] = {A.z, B.y, C.x, C.w};
#pragma unroll
            for (int k = 0; k < 4; k++)
                acc += point_rot(X[k], Y[k], Z[k], m, s_bits);
        }
        if (tail && bid == 0 && threadIdx.x < tail) {
            int i = npts - tail + threadIdx.x;
            acc += point_rot(sp[3*i], sp[3*i+1], sp[3*i+2], m, s_bits);
        }
    }

    // deterministic block reduction
#pragma unroll
    for (int o = 16; o; o >>= 1)
        acc += __shfl_xor_sync(0xFFFFFFFFu, acc, o);
    int lane = threadIdx.x & 31;
    int wid  = threadIdx.x >> 5;
    if (lane == 0) s_red[wid] = acc;
    __syncthreads();
    if (threadIdx.x == 0) {
        float v = 0.0f;
#pragma unroll
        for (int w = 0; w < NT / 32; w++) v += s_red[w];
        g_partials[blockIdx.x] = v;
        __threadfence();
        unsigned old = atomicAdd(&g_counter, 1);
        s_last = (old == (unsigned)(gridDim.x - 1));
    }
    __syncthreads();

    // last-arriving block performs the final deterministic reduction
    if (s_last) {
        __threadfence();
        float v = 0.0f;
        for (int i = threadIdx.x; i < NB; i += NT)
            v += g_partials[i];
#pragma unroll
        for (int o = 16; o; o >>= 1)
            v += __shfl_xor_sync(0xFFFFFFFFu, v, o);
        if (lane == 0) s_red[wid] = v;
        __syncthreads();
        if (threadIdx.x == 0) {
            float u = 0.0f;
#pragma unroll
            for (int w = 0; w < NT / 32; w++) u += s_red[w];
            out[0] = u / (float)npts;
        }
    }
}

// ---- launch ------------------------------------------------------------------
extern "C" void kernel_launch(void* const* d_in, const int* in_sizes, int n_in,
                              void* d_out, int out_size) {
    const float* sp     = (const float*)d_in[0];   // sample_points (N,3)
    const float* cp     = (const float*)d_in[1];   // closest_points (R^3,3)
    const int*   vox    = (const int*)  d_in[2];   // voxels (R^3,)
    const float* planes = (const float*)d_in[3];   // (3,4)
    const float* axes   = (const float*)d_in[4];   // (3,4)
    int npts = in_sizes[0] / 3;

    prep_k<<<(R3 + 255) / 256, 256>>>(cp, vox, planes, axes);
    symmetry_main_k<<<NB, NT>>>(sp, npts, (float*)d_out);
}

// round 7
// speedup vs baseline: 1.9644x; 1.1328x over previous
#include <cuda_runtime.h>

#define RES      64
#define R3       (RES * RES * RES)      // 262144
#define NWORDS   (R3 / 32)              // 8192  (32 KB bitmask)
#define NB       740                    // 148 SMs * 5 blocks
#define NHALF    (NB / 2)               // 370 per transform family
#define NT       256

// ---- scratch (no allocations allowed) --------------------------------------
__device__ float4   g_table[R3];        // closest point per voxel (w unused)
__device__ unsigned g_bits[NWORDS];     // voxel occupancy bitmask
__device__ float    g_params[48];       // [t*5+j]: refl ; [16+t*9+j]: rot matrix
__device__ float    g_partials[NB];
__device__ int      g_counter;

// ---- prep: params + float4 table + bitmask + counter reset (one kernel) -----
__global__ void prep_k(const float* __restrict__ cp,
                       const int*   __restrict__ vox,
                       const float* __restrict__ planes,
                       const float* __restrict__ axes) {
    int i = blockIdx.x * blockDim.x + threadIdx.x;
    if (i == 0) {
        g_counter = 0;
#pragma unroll
        for (int t = 0; t < 3; t++) {
            float nx = planes[4*t+0], ny = planes[4*t+1],
                  nz = planes[4*t+2], d  = planes[4*t+3];
            float s = 2.0f / (nx*nx + ny*ny + nz*nz);
            g_params[t*5+0] = nx;
            g_params[t*5+1] = ny;
            g_params[t*5+2] = nz;
            g_params[t*5+3] = s;
            g_params[t*5+4] = s * d;
        }
#pragma unroll
        for (int t = 0; t < 3; t++) {
            float w = axes[4*t+0], x = axes[4*t+1],
                  y = axes[4*t+2], z = axes[4*t+3];
            // q p q* (pure p, q unnormalized) = [(w^2-|v|^2)I + 2 v v^T + 2 w [v]x] p
            float* m = &g_params[16 + t*9];
            m[0] = w*w + x*x - y*y - z*z;
            m[1] = 2.0f * (x*y - w*z);
            m[2] = 2.0f * (x*z + w*y);
            m[3] = 2.0f * (x*y + w*z);
            m[4] = w*w - x*x + y*y - z*z;
            m[5] = 2.0f * (y*z - w*x);
            m[6] = 2.0f * (x*z - w*y);
            m[7] = 2.0f * (y*z + w*x);
            m[8] = w*w - x*x - y*y + z*z;
        }
    }
    if (i < R3) {
        float4 v;
        v.x = cp[3*i + 0];
        v.y = cp[3*i + 1];
        v.z = cp[3*i + 2];
        v.w = 0.0f;
        g_table[i] = v;
    }
    if (i < NWORDS) {
        unsigned w = 0u;
#pragma unroll 8
        for (int j = 0; j < 32; j++)
            if (vox[i*32 + j] != 0) w |= (1u << j);
        g_bits[i] = w;
    }
}

// ---- voxel index from transformed coords ------------------------------------
__device__ __forceinline__ int vidx(float x, float y, float z) {
    int ix = min(max(__float2int_rd(x * 64.0f), 0), 63);
    int iy = min(max(__float2int_rd(y * 64.0f), 0), 63);
    int iz = min(max(__float2int_rd(z * 64.0f), 0), 63);
    return (ix << 12) | (iy << 6) | iz;
}

// 3 predicated taps for one point. Dead lanes issue NO load (no broadcast wf)
// and default the gathered point to the query point -> dist = 0 with no mask.
__device__ __forceinline__ float taps3(const float tx[3], const float ty[3],
                                       const float tz[3],
                                       const unsigned* __restrict__ s_bits) {
    int      idx[3];
    unsigned bit[3];
#pragma unroll
    for (int t = 0; t < 3; t++) {
        idx[t] = vidx(tx[t], ty[t], tz[t]);
        bit[t] = (s_bits[idx[t] >> 5] >> (idx[t] & 31)) & 1u;
    }
    float acc = 0.0f;
#pragma unroll
    for (int t = 0; t < 3; t++) {
        float cx = tx[t], cy = ty[t], cz = tz[t], cw = 0.0f;
        const float4* p = &g_table[idx[t]];
        asm("{\n\t"
            ".reg .pred lp;\n\t"
            "setp.ne.u32 lp, %4, 0;\n\t"
            "@lp ld.global.nc.v4.f32 {%0, %1, %2, %3}, [%5];\n\t"
            "}"
            : "+f"(cx), "+f"(cy), "+f"(cz), "+f"(cw)
            : "r"(bit[t]), "l"(p));
        float dx = tx[t] - cx, dy = ty[t] - cy, dz = tz[t] - cz;
        float d2 = fmaxf(fmaf(dx, dx, fmaf(dy, dy, dz * dz)), 1e-30f);
        acc += d2 * rsqrtf(d2);                // sqrt(d2); 0 for dead lanes
    }
    return acc;
}

__device__ __forceinline__ float point_refl(float x, float y, float z,
                                            const float pn[3][5],
                                            const unsigned* __restrict__ s_bits) {
    float tx[3], ty[3], tz[3];
#pragma unroll
    for (int t = 0; t < 3; t++) {
        float dot  = fmaf(x, pn[t][0], fmaf(y, pn[t][1], z * pn[t][2]));
        float coef = fmaf(dot, pn[t][3], pn[t][4]);
        tx[t] = fmaf(-coef, pn[t][0], x);
        ty[t] = fmaf(-coef, pn[t][1], y);
        tz[t] = fmaf(-coef, pn[t][2], z);
    }
    return taps3(tx, ty, tz, s_bits);
}

__device__ __forceinline__ float point_rot(float x, float y, float z,
                                           const float m[3][9],
                                           const unsigned* __restrict__ s_bits) {
    float tx[3], ty[3], tz[3];
#pragma unroll
    for (int t = 0; t < 3; t++) {
        tx[t] = fmaf(x, m[t][0], fmaf(y, m[t][1], z * m[t][2]));
        ty[t] = fmaf(x, m[t][3], fmaf(y, m[t][4], z * m[t][5]));
        tz[t] = fmaf(x, m[t][6], fmaf(y, m[t][7], z * m[t][8]));
    }
    return taps3(tx, ty, tz, s_bits);
}

// ---- main kernel: blocks [0,NHALF) do reflections, [NHALF,NB) rotations ------
__global__ void __launch_bounds__(NT, 5)
symmetry_main_k(const float* __restrict__ sp, int npts, float* __restrict__ out) {
    __shared__ unsigned s_bits[NWORDS];   // 32 KB
    __shared__ float    s_red[NT / 32];
    __shared__ bool     s_last;

    for (int i = threadIdx.x; i < NWORDS; i += NT)
        s_bits[i] = g_bits[i];
    __syncthreads();

    const bool is_rot = (blockIdx.x >= NHALF);
    const int  bid    = is_rot ? (blockIdx.x - NHALF) : blockIdx.x;

    const float4* sp4 = (const float4*)sp;
    const int ngroups = npts >> 2;     // 4 points = 3 float4
    const int stride  = NHALF * NT;
    const int tail    = npts & 3;
    float acc = 0.0f;

    if (!is_rot) {
        float pn[3][5];
#pragma unroll
        for (int t = 0; t < 3; t++)
#pragma unroll
            for (int j = 0; j < 5; j++) pn[t][j] = g_params[t*5 + j];

        for (int g = bid * NT + threadIdx.x; g < ngroups; g += stride) {
            float4 A = __ldg(&sp4[3*g + 0]);
            float4 B = __ldg(&sp4[3*g + 1]);
            float4 C = __ldg(&sp4[3*g + 2]);
            float X[4] = {A.x, A.w, B.z, C.y};
            float Y[4] = {A.y, B.x, B.w, C.z};
            float Z[4] = {A.z, B.y, C.x, C.w};
#pragma unroll
            for (int k = 0; k < 4; k++)
                acc += point_refl(X[k], Y[k], Z[k], pn, s_bits);
        }
        if (tail && bid == 0 && threadIdx.x < tail) {
            int i = npts - tail + threadIdx.x;
            acc += point_refl(sp[3*i], sp[3*i+1], sp[3*i+2], pn, s_bits);
        }
    } else {
        float m[3][9];
#pragma unroll
        for (int t = 0; t < 3; t++)
#pragma unroll
            for (int j = 0; j < 9; j++) m[t][j] = g_params[16 + t*9 + j];

        for (int g = bid * NT + threadIdx.x; g < ngroups; g += stride) {
            float4 A = __ldg(&sp4[3*g + 0]);
            float4 B = __ldg(&sp4[3*g + 1]);
            float4 C = __ldg(&sp4[3*g + 2]);
            float X[4] = {A.x, A.w, B.z, C.y};
            float Y[4] = {A.y, B.x, B.w, C.z};
            float Z[4] = {A.z, B.y, C.x, C.w};
#pragma unroll
            for (int k = 0; k < 4; k++)
                acc += point_rot(X[k], Y[k], Z[k], m, s_bits);
        }
        if (tail && bid == 0 && threadIdx.x < tail) {
            int i = npts - tail + threadIdx.x;
            acc += point_rot(sp[3*i], sp[3*i+1], sp[3*i+2], m, s_bits);
        }
    }

    // deterministic block reduction
#pragma unroll
    for (int o = 16; o; o >>= 1)
        acc += __shfl_xor_sync(0xFFFFFFFFu, acc, o);
    int lane = threadIdx.x & 31;
    int wid  = threadIdx.x >> 5;
    if (lane == 0) s_red[wid] = acc;
    __syncthreads();
    if (threadIdx.x == 0) {
        float v = 0.0f;
#pragma unroll
        for (int w = 0; w < NT / 32; w++) v += s_red[w];
        g_partials[blockIdx.x] = v;
        __threadfence();
        unsigned old = atomicAdd(&g_counter, 1);
        s_last = (old == (unsigned)(gridDim.x - 1));
    }
    __syncthreads();

    // last-arriving block performs the final deterministic reduction
    if (s_last) {
        __threadfence();
        float v = 0.0f;
        for (int i = threadIdx.x; i < NB; i += NT)
            v += g_partials[i];
#pragma unroll
        for (int o = 16; o; o >>= 1)
            v += __shfl_xor_sync(0xFFFFFFFFu, v, o);
        if (lane == 0) s_red[wid] = v;
        __syncthreads();
        if (threadIdx.x == 0) {
            float u = 0.0f;
#pragma unroll
            for (int w = 0; w < NT / 32; w++) u += s_red[w];
            out[0] = u / (float)npts;
        }
    }
}

// ---- launch ------------------------------------------------------------------
extern "C" void kernel_launch(void* const* d_in, const int* in_sizes, int n_in,
                              void* d_out, int out_size) {
    const float* sp     = (const float*)d_in[0];   // sample_points (N,3)
    const float* cp     = (const float*)d_in[1];   // closest_points (R^3,3)
    const int*   vox    = (const int*)  d_in[2];   // voxels (R^3,)
    const float* planes = (const float*)d_in[3];   // (3,4)
    const float* axes   = (const float*)d_in[4];   // (3,4)
    int npts = in_sizes[0] / 3;

    prep_k<<<(R3 + 255) / 256, 256>>>(cp, vox, planes, axes);
    symmetry_main_k<<<NB, NT>>>(sp, npts, (float*)d_out);
}